// round 1
// baseline (speedup 1.0000x reference)
#include <cuda_runtime.h>

#define NB 32
#define HH 640
#define WW 640
#define HW (HH * WW)
#define TOT (NB * HW)
#define NCHW (NB * 2 * HW)

// Ping-pong scratch displacement buffers, interleaved float2 [N,H,W,(x,y)].
__device__ float2 g_bufA[TOT];
__device__ float2 g_bufB[TOT];

// Bilinear sample (border clamp, align_corners=True) from an interleaved
// per-batch float2 field b[H*W], at normalized coords (gx+dx, gy+dy).
__device__ __forceinline__ float2 bilerp2(const float2* __restrict__ b,
                                          float gx, float gy,
                                          float dx, float dy) {
    float px = (gx + dx + 1.0f) * (0.5f * (float)(WW - 1));
    float py = (gy + dy + 1.0f) * (0.5f * (float)(HH - 1));
    px = fminf(fmaxf(px, 0.0f), (float)(WW - 1));
    py = fminf(fmaxf(py, 0.0f), (float)(HH - 1));
    float x0f = floorf(px);
    float y0f = floorf(py);
    int x0 = (int)x0f;
    int y0 = (int)y0f;
    int x1 = min(x0 + 1, WW - 1);
    int y1 = min(y0 + 1, HH - 1);
    float wx = px - x0f;
    float wy = py - y0f;
    float2 v00 = b[y0 * WW + x0];
    float2 v01 = b[y0 * WW + x1];
    float2 v10 = b[y1 * WW + x0];
    float2 v11 = b[y1 * WW + x1];
    float topx = v00.x * (1.0f - wx) + v01.x * wx;
    float topy = v00.y * (1.0f - wx) + v01.y * wx;
    float botx = v10.x * (1.0f - wx) + v11.x * wx;
    float boty = v10.y * (1.0f - wx) + v11.y * wx;
    return make_float2(topx * (1.0f - wy) + botx * wy,
                       topy * (1.0f - wy) + boty * wy);
}

// Iteration 0: disp0 = v * 2^-32 (computed on the fly from planar v), then one
// scaling-and-squaring step; result written interleaved into g_bufA.
__global__ __launch_bounds__(256) void k_first(const float* __restrict__ v,
                                               const float2* __restrict__ idg,
                                               float2* __restrict__ dst) {
    int idx = blockIdx.x * blockDim.x + threadIdx.x;
    if (idx >= TOT) return;
    int n = idx / HW;
    int p = idx - n * HW;

    const float* vx = v + (size_t)n * 2 * HW;
    const float* vy = vx + HW;
    const float S = 0x1p-32f;

    float dx = vx[p] * S;
    float dy = vy[p] * S;
    float2 g = idg[p];

    float px = (g.x + dx + 1.0f) * (0.5f * (float)(WW - 1));
    float py = (g.y + dy + 1.0f) * (0.5f * (float)(HH - 1));
    px = fminf(fmaxf(px, 0.0f), (float)(WW - 1));
    py = fminf(fmaxf(py, 0.0f), (float)(HH - 1));
    float x0f = floorf(px);
    float y0f = floorf(py);
    int x0 = (int)x0f;
    int y0 = (int)y0f;
    int x1 = min(x0 + 1, WW - 1);
    int y1 = min(y0 + 1, HH - 1);
    float wx = px - x0f;
    float wy = py - y0f;

    float sx, sy;
    {
        float a00 = vx[y0 * WW + x0] * S, a01 = vx[y0 * WW + x1] * S;
        float a10 = vx[y1 * WW + x0] * S, a11 = vx[y1 * WW + x1] * S;
        float top = a00 * (1.0f - wx) + a01 * wx;
        float bot = a10 * (1.0f - wx) + a11 * wx;
        sx = top * (1.0f - wy) + bot * wy;
    }
    {
        float a00 = vy[y0 * WW + x0] * S, a01 = vy[y0 * WW + x1] * S;
        float a10 = vy[y1 * WW + x0] * S, a11 = vy[y1 * WW + x1] * S;
        float top = a00 * (1.0f - wx) + a01 * wx;
        float bot = a10 * (1.0f - wx) + a11 * wx;
        sy = top * (1.0f - wy) + bot * wy;
    }

    dst[idx] = make_float2(dx + sx, dy + sy);
}

// Middle iterations: interleaved -> interleaved ping-pong.
__global__ __launch_bounds__(256) void k_step(const float2* __restrict__ src,
                                              const float2* __restrict__ idg,
                                              float2* __restrict__ dst) {
    int idx = blockIdx.x * blockDim.x + threadIdx.x;
    if (idx >= TOT) return;
    int n = idx / HW;
    int p = idx - n * HW;

    const float2* b = src + (size_t)n * HW;
    float2 d = b[p];
    float2 g = idg[p];
    float2 s = bilerp2(b, g.x, g.y, d.x, d.y);
    dst[idx] = make_float2(d.x + s.x, d.y + s.y);
}

// Final iteration (iter 31): does the step and writes both outputs planar:
//   out[0        : NCHW) = transformation = idg(transposed) + disp
//   out[NCHW     : 2*NCHW) = displacement
__global__ __launch_bounds__(256) void k_last(const float2* __restrict__ src,
                                              const float2* __restrict__ idg,
                                              float* __restrict__ out) {
    int idx = blockIdx.x * blockDim.x + threadIdx.x;
    if (idx >= TOT) return;
    int n = idx / HW;
    int p = idx - n * HW;

    const float2* b = src + (size_t)n * HW;
    float2 d = b[p];
    float2 g = idg[p];
    float2 s = bilerp2(b, g.x, g.y, d.x, d.y);
    float ndx = d.x + s.x;
    float ndy = d.y + s.y;

    size_t base = (size_t)n * 2 * HW + p;
    out[base] = g.x + ndx;                 // transformation ch0
    out[base + HW] = g.y + ndy;            // transformation ch1
    out[(size_t)NCHW + base] = ndx;        // displacement ch0
    out[(size_t)NCHW + base + HW] = ndy;   // displacement ch1
}

extern "C" void kernel_launch(void* const* d_in, const int* in_sizes, int n_in,
                              void* d_out, int out_size) {
    const float* v = (const float*)d_in[0];
    const float2* idg = (const float2*)d_in[1];  // [1,H,W,2] interleaved
    float* out = (float*)d_out;

    float2 *A, *B;
    cudaGetSymbolAddress((void**)&A, g_bufA);
    cudaGetSymbolAddress((void**)&B, g_bufB);

    const int threads = 256;
    const int blocks = (TOT + threads - 1) / threads;

    // Iteration 0 (reads v planar, scale folded in) -> A
    k_first<<<blocks, threads>>>(v, idg, A);

    // Iterations 1..30 ping-pong
    float2* src = A;
    float2* dst = B;
    for (int it = 1; it <= 30; ++it) {
        k_step<<<blocks, threads>>>(src, idg, dst);
        float2* t = src; src = dst; dst = t;
    }
    // after it=30, result is in `src` (== A)

    // Iteration 31 fused with output write (planar transformation + displacement)
    k_last<<<blocks, threads>>>(src, idg, out);
}

// round 3
// speedup vs baseline: 1.0530x; 1.0530x over previous
#include <cuda_runtime.h>

#define NB 32
#define HH 640
#define WW 640
#define HW (HH * WW)
#define CH 8                    // batches per chunk (scratch = 2*26MB, L2-resident)
#define NCHUNK (NB / CH)
#define NCHW (NB * 2 * HW)

// Chunk-sized ping-pong scratch, interleaved float2 [CH,H,W,(x,y)].
__device__ float2 g_bufA[CH * HW];
__device__ float2 g_bufB[CH * HW];

// Bilinear sample (border clamp, align_corners=True) from interleaved field
// b[H*W] at normalized coords (tx,ty). EXACT round-1 arithmetic.
__device__ __forceinline__ float2 samp(const float2* __restrict__ b,
                                       float tx, float ty) {
    float px = (tx + 1.0f) * (0.5f * (float)(WW - 1));
    float py = (ty + 1.0f) * (0.5f * (float)(HH - 1));
    px = fminf(fmaxf(px, 0.0f), (float)(WW - 1));
    py = fminf(fmaxf(py, 0.0f), (float)(HH - 1));
    float x0f = floorf(px);
    float y0f = floorf(py);
    int x0 = (int)x0f;
    int y0 = (int)y0f;
    int x1 = min(x0 + 1, WW - 1);
    int y1 = min(y0 + 1, HH - 1);
    float wx = px - x0f;
    float wy = py - y0f;
    float2 v00 = b[y0 * WW + x0];
    float2 v01 = b[y0 * WW + x1];
    float2 v10 = b[y1 * WW + x0];
    float2 v11 = b[y1 * WW + x1];
    float topx = v00.x * (1.0f - wx) + v01.x * wx;
    float topy = v00.y * (1.0f - wx) + v01.y * wx;
    float botx = v10.x * (1.0f - wx) + v11.x * wx;
    float boty = v10.y * (1.0f - wx) + v11.y * wx;
    return make_float2(topx * (1.0f - wy) + botx * wy,
                       topy * (1.0f - wy) + boty * wy);
}

// Planar sampler over v with scale S applied to each tap (round-1 exact).
__device__ __forceinline__ float2 sampP(const float* __restrict__ vx,
                                        const float* __restrict__ vy,
                                        float tx, float ty, float S) {
    float px = (tx + 1.0f) * (0.5f * (float)(WW - 1));
    float py = (ty + 1.0f) * (0.5f * (float)(HH - 1));
    px = fminf(fmaxf(px, 0.0f), (float)(WW - 1));
    py = fminf(fmaxf(py, 0.0f), (float)(HH - 1));
    float x0f = floorf(px);
    float y0f = floorf(py);
    int x0 = (int)x0f;
    int y0 = (int)y0f;
    int x1 = min(x0 + 1, WW - 1);
    int y1 = min(y0 + 1, HH - 1);
    float wx = px - x0f;
    float wy = py - y0f;
    float sx, sy;
    {
        float a00 = vx[y0 * WW + x0] * S, a01 = vx[y0 * WW + x1] * S;
        float a10 = vx[y1 * WW + x0] * S, a11 = vx[y1 * WW + x1] * S;
        float top = a00 * (1.0f - wx) + a01 * wx;
        float bot = a10 * (1.0f - wx) + a11 * wx;
        sx = top * (1.0f - wy) + bot * wy;
    }
    {
        float a00 = vy[y0 * WW + x0] * S, a01 = vy[y0 * WW + x1] * S;
        float a10 = vy[y1 * WW + x0] * S, a11 = vy[y1 * WW + x1] * S;
        float top = a00 * (1.0f - wx) + a01 * wx;
        float bot = a10 * (1.0f - wx) + a11 * wx;
        sy = top * (1.0f - wy) + bot * wy;
    }
    return make_float2(sx, sy);
}

// Iteration 0 for one chunk: disp0 = v*2^-32, one step, write interleaved.
// One 640-px row per 320-thread block, 2 px per thread.
__global__ __launch_bounds__(320) void k_first(const float* __restrict__ v,
                                               const float2* __restrict__ idg,
                                               float2* __restrict__ dst) {
    int row = blockIdx.x;            // 0 .. CH*HH-1
    int n = row / HH;
    int y = row - n * HH;
    const float* vx = v + (size_t)n * 2 * HW;
    const float* vy = vx + HW;
    const float S = 0x1p-32f;

    int x = threadIdx.x * 2;
    int p = y * WW + x;

    float4 g = *reinterpret_cast<const float4*>(idg + p);  // (g0x,g0y,g1x,g1y)

    float d0x = vx[p] * S,     d0y = vy[p] * S;
    float d1x = vx[p + 1] * S, d1y = vy[p + 1] * S;

    float2 s0 = sampP(vx, vy, g.x + d0x, g.y + d0y, S);
    float2 s1 = sampP(vx, vy, g.z + d1x, g.w + d1y, S);

    float4 r = make_float4(d0x + s0.x, d0y + s0.y, d1x + s1.x, d1y + s1.y);
    *reinterpret_cast<float4*>(dst + (size_t)n * HW + p) = r;
}

// Middle iterations: interleaved -> interleaved, chunk ping-pong.
__global__ __launch_bounds__(320) void k_step(const float2* __restrict__ src,
                                              const float2* __restrict__ idg,
                                              float2* __restrict__ dst) {
    int row = blockIdx.x;            // 0 .. CH*HH-1
    int n = row / HH;
    int y = row - n * HH;
    const float2* b = src + (size_t)n * HW;

    int x = threadIdx.x * 2;
    int p = y * WW + x;
    float4 d = *reinterpret_cast<const float4*>(b + p);
    float4 g = *reinterpret_cast<const float4*>(idg + p);

    float2 s0 = samp(b, g.x + d.x, g.y + d.y);
    float2 s1 = samp(b, g.z + d.z, g.w + d.w);

    float4 r = make_float4(d.x + s0.x, d.y + s0.y, d.z + s1.x, d.w + s1.y);
    *reinterpret_cast<float4*>(dst + (size_t)n * HW + p) = r;
}

// Final iteration for one chunk: step + planar output write.
//   out[0:NCHW)        = transformation = idgrid + disp
//   out[NCHW:2*NCHW)   = displacement
__global__ __launch_bounds__(320) void k_last(const float2* __restrict__ src,
                                              const float2* __restrict__ idg,
                                              float* __restrict__ out,
                                              int nglobBase) {
    int row = blockIdx.x;
    int n = row / HH;
    int y = row - n * HH;
    const float2* b = src + (size_t)n * HW;

    int x = threadIdx.x * 2;
    int p = y * WW + x;
    float4 d = *reinterpret_cast<const float4*>(b + p);
    float4 g = *reinterpret_cast<const float4*>(idg + p);

    float2 s0 = samp(b, g.x + d.x, g.y + d.y);
    float2 s1 = samp(b, g.z + d.z, g.w + d.w);

    float n0x = d.x + s0.x, n0y = d.y + s0.y;
    float n1x = d.z + s1.x, n1y = d.w + s1.y;

    size_t base = (size_t)(nglobBase + n) * 2 * HW + p;
    // transformation ch0 (x), ch1 (y)
    *reinterpret_cast<float2*>(out + base)      = make_float2(g.x + n0x, g.z + n1x);
    *reinterpret_cast<float2*>(out + base + HW) = make_float2(g.y + n0y, g.w + n1y);
    // displacement ch0, ch1
    *reinterpret_cast<float2*>(out + NCHW + base)      = make_float2(n0x, n1x);
    *reinterpret_cast<float2*>(out + NCHW + base + HW) = make_float2(n0y, n1y);
}

extern "C" void kernel_launch(void* const* d_in, const int* in_sizes, int n_in,
                              void* d_out, int out_size) {
    const float* v = (const float*)d_in[0];
    const float2* idg = (const float2*)d_in[1];  // [1,H,W,2] interleaved
    float* out = (float*)d_out;

    float2 *A, *B;
    cudaGetSymbolAddress((void**)&A, g_bufA);
    cudaGetSymbolAddress((void**)&B, g_bufB);

    const int threads = 320;             // one 640-px row, 2 px/thread
    const int blocks = CH * HH;          // 5120 blocks per chunk launch

    for (int c = 0; c < NCHUNK; ++c) {
        const float* vC = v + (size_t)c * CH * 2 * HW;

        // Iteration 0 (reads v planar, scale folded) -> A
        k_first<<<blocks, threads>>>(vC, idg, A);

        // Iterations 1..30 ping-pong within L2-resident scratch
        float2* src = A;
        float2* dst = B;
        for (int it = 1; it <= 30; ++it) {
            k_step<<<blocks, threads>>>(src, idg, dst);
            float2* t = src; src = dst; dst = t;
        }
        // After 30 steps result is back in A (src == A)

        // Iteration 31 fused with planar output write
        k_last<<<blocks, threads>>>(src, idg, out, c * CH);
    }
}